// round 9
// baseline (speedup 1.0000x reference)
#include <cuda_runtime.h>
#include <cstdint>

#define BB 64
#define NN 1024

// Output layout (flattened reference tuple, all float32):
#define OFF_DONE 0
#define OFF_NM   1
#define OFF_ADJ  (1 + BB*NN)
#define OFF_FA   (OFF_ADJ + (size_t)BB*NN*NN)
#define OFF_PT   (OFF_FA + BB)
#define OFF_STEP (OFF_PT + BB)

__device__ float g_fp[BB * NN];     // fpresent[b, i]
__device__ float g_dlast[NN];       // dist[:, N-1] contiguous
__device__ float g_nmlast[BB];      // new_mask[b, N-1] (for `done` reduction)

// One block gathers the strided dist column ONCE (previously all 64 k_prep
// blocks redundantly did this stride-4KB walk).
__global__ void k_pre(const float* __restrict__ dist) {
    int j = threadIdx.x;
    g_dlast[j] = dist[(size_t)j * NN + (NN - 1)];
}

__global__ void k_prep(const float* __restrict__ inputs,
                       const float* __restrict__ dist,
                       const float* __restrict__ mask,
                       const float* __restrict__ ptime,
                       const int*   __restrict__ pres,
                       const int*   __restrict__ fut,
                       float* out)
{
    int b = blockIdx.x;
    int j = threadIdx.x;

    int   pa = pres[b];
    float pt = ptime[b];

    float4 in4 = *reinterpret_cast<const float4*>(inputs + ((size_t)(b * NN + j)) * 4);
    float op = in4.x, cl = in4.y, dur = in4.z;
    float T0 = inputs[3];

    float dlast  = g_dlast[j];                  // coalesced (k_pre ran first)
    float arrive = dist[(size_t)pa * NN + j] + pt;
    float wait   = fmaxf(0.0f, op - arrive);
    float t      = arrive + wait;

    bool c1 = t <= cl;
    bool c2 = ((t + dur) + dlast) <= T0;

    float m = mask[b * NN + j];
    if (j == pa) m = 0.0f;
    float nm = (c1 && c2) ? m : 0.0f;

    float fpres = t + dur;

    out[OFF_NM + b * NN + j] = nm;
    g_fp[b * NN + j] = fpres;
    if (j == NN - 1) g_nmlast[b] = nm;

    int fb = fut[b];
    if (j == fb) out[OFF_PT + b] = fpres;
    if (j == 0) {
        out[OFF_FA + b]   = (float)fb;
        out[OFF_STEP + b] = 1.0f;
    }
}

// adj kernel — R1 champion interior (fully coalesced scalar, no smem, no
// launch bounds: ptxas free to front-batch loads with a rich register file),
// with WRITE-THROUGH stores (__stwt): the 268MB write-once stream bypasses
// L2 dirty-line allocation, removing writeback backpressure on the store path.
#define BT 4
#define RR 8

__global__ __launch_bounds__(256) void k_adj(const float* __restrict__ inputs,
                                             const float* __restrict__ dist,
                                             float* out)
{
    const int ITILES = NN / RR;                 // 128
    int itile = blockIdx.x & (ITILES - 1);
    int b0    = (blockIdx.x / ITILES) * BT;
    int i0    = itile * RR;
    int tid   = threadIdx.x;

    if (blockIdx.x == 0 && tid == 0) {
        float any = 0.0f;
#pragma unroll
        for (int b = 0; b < BB; b++) any = fmaxf(any, g_nmlast[b]);
        out[OFF_DONE] = (any > 0.0f) ? 0.0f : 1.0f;
    }

    float dl[4];
#pragma unroll
    for (int q = 0; q < 4; q++) dl[q] = g_dlast[tid + 256 * q];

    const float* nm_base = out + OFF_NM;

    for (int bb = 0; bb < BT; bb++) {
        int b = b0 + bb;

        float op[4], cl[4], du[4], nm[4];
#pragma unroll
        for (int q = 0; q < 4; q++) {
            int j = tid + 256 * q;
            float4 in4 = *reinterpret_cast<const float4*>(
                inputs + ((size_t)(b * NN + j)) * 4);
            op[q] = in4.x; cl[q] = in4.y; du[q] = in4.z;
            nm[q] = nm_base[b * NN + j];
        }
        float Tb = inputs[((size_t)b * NN) * 4 + 3];

#pragma unroll
        for (int r = 0; r < RR; r++) {
            int   i  = i0 + r;
            float fp = g_fp[b * NN + i];
            const float* drow = dist + (size_t)i * NN;
            float* orow = out + OFF_ADJ + ((size_t)(b * NN + i)) * NN;

#pragma unroll
            for (int q = 0; q < 4; q++) {
                int j = tid + 256 * q;
                float arr2 = drow[j] + fp;
                float w    = fmaxf(0.0f, op[q] - arr2);
                float s    = arr2 + w;
                bool a1 = s <= cl[q];
                bool a2 = ((s + du[q]) + dl[q]) <= Tb;
                float v = (a1 && a2) ? nm[q] : 0.0f;
                if (j == i) v = 1.0f;
                __stwt(orow + j, v);
            }
        }
    }
}

extern "C" void kernel_launch(void* const* d_in, const int* in_sizes, int n_in,
                              void* d_out, int out_size)
{
    const float* inputs = (const float*)d_in[0];   // (B, N, 4) f32
    const float* dist   = (const float*)d_in[1];   // (N, N)   f32
    const float* mask   = (const float*)d_in[2];   // (B, N)   f32
    const float* ptime  = (const float*)d_in[3];   // (B, 1)   f32
    const int*   pres   = (const int*)d_in[4];     // (B,)     i32
    const int*   fut    = (const int*)d_in[5];     // (B,)     i32
    float* out = (float*)d_out;

    k_pre<<<1, NN>>>(dist);
    k_prep<<<BB, NN>>>(inputs, dist, mask, ptime, pres, fut, out);
    k_adj<<<(NN / RR) * (BB / BT), 256>>>(inputs, dist, out);
}

// round 10
// speedup vs baseline: 1.2228x; 1.2228x over previous
#include <cuda_runtime.h>
#include <cstdint>

#define BB 64
#define NN 1024

// Output layout (flattened reference tuple, all float32):
#define OFF_DONE 0
#define OFF_NM   1
#define OFF_ADJ  (1 + BB*NN)
#define OFF_FA   (OFF_ADJ + (size_t)BB*NN*NN)
#define OFF_PT   (OFF_FA + BB)
#define OFF_STEP (OFF_PT + BB)

__device__ float g_fp[BB * NN];     // fpresent[b, i]
__device__ float g_dlast[NN];       // dist[:, N-1] contiguous
__device__ float g_nmlast[BB];      // new_mask[b, N-1] (for `done` reduction)

__global__ void k_prep(const float* __restrict__ inputs,
                       const float* __restrict__ dist,
                       const float* __restrict__ mask,
                       const float* __restrict__ ptime,
                       const int*   __restrict__ pres,
                       const int*   __restrict__ fut,
                       float* out)
{
    int b = blockIdx.x;
    int j = threadIdx.x;

    int   pa = pres[b];
    float pt = ptime[b];

    float4 in4 = *reinterpret_cast<const float4*>(inputs + ((size_t)(b * NN + j)) * 4);
    float op = in4.x, cl = in4.y, dur = in4.z;
    float T0 = inputs[3];

    float dlast  = dist[(size_t)j * NN + (NN - 1)];
    float arrive = dist[(size_t)pa * NN + j] + pt;
    float wait   = fmaxf(0.0f, op - arrive);
    float t      = arrive + wait;

    bool c1 = t <= cl;
    bool c2 = ((t + dur) + dlast) <= T0;

    float m = mask[b * NN + j];
    if (j == pa) m = 0.0f;
    float nm = (c1 && c2) ? m : 0.0f;

    float fpres = t + dur;

    out[OFF_NM + b * NN + j] = nm;
    g_fp[b * NN + j] = fpres;
    if (b == 0) g_dlast[j] = dlast;
    if (j == NN - 1) g_nmlast[b] = nm;

    int fb = fut[b];
    if (j == fb) out[OFF_PT + b] = fpres;
    if (j == 0) {
        out[OFF_FA + b]   = (float)fb;
        out[OFF_STEP + b] = 1.0f;
    }
}

// adj kernel — champion interior (fully coalesced scalar, no smem, plain
// stores, ptxas free on registers), retiled RR=16/BT=8 to HALVE the L2 read
// traffic (dist 64->32MB, inputs 139->68MB, nm 32->16MB): the convergence of
// all interiors at ~62-72us matches the chip LTS byte-throughput cap, so the
// lever is bytes, not instructions.
#define BT 8
#define RR 16

__global__ __launch_bounds__(256) void k_adj(const float* __restrict__ inputs,
                                             const float* __restrict__ dist,
                                             float* out)
{
    const int ITILES = NN / RR;                 // 64
    int itile = blockIdx.x & (ITILES - 1);
    int b0    = (blockIdx.x / ITILES) * BT;
    int i0    = itile * RR;
    int tid   = threadIdx.x;

    if (blockIdx.x == 0 && tid == 0) {
        float any = 0.0f;
#pragma unroll
        for (int b = 0; b < BB; b++) any = fmaxf(any, g_nmlast[b]);
        out[OFF_DONE] = (any > 0.0f) ? 0.0f : 1.0f;
    }

    float dl[4];
#pragma unroll
    for (int q = 0; q < 4; q++) dl[q] = g_dlast[tid + 256 * q];

    const float* nm_base = out + OFF_NM;

    for (int bb = 0; bb < BT; bb++) {
        int b = b0 + bb;

        float op[4], cl[4], du[4], nm[4];
#pragma unroll
        for (int q = 0; q < 4; q++) {
            int j = tid + 256 * q;
            float4 in4 = *reinterpret_cast<const float4*>(
                inputs + ((size_t)(b * NN + j)) * 4);
            op[q] = in4.x; cl[q] = in4.y; du[q] = in4.z;
            nm[q] = nm_base[b * NN + j];
        }
        float Tb = inputs[((size_t)b * NN) * 4 + 3];

#pragma unroll
        for (int r = 0; r < RR; r++) {
            int   i  = i0 + r;
            float fp = g_fp[b * NN + i];
            const float* drow = dist + (size_t)i * NN;
            float* orow = out + OFF_ADJ + ((size_t)(b * NN + i)) * NN;

#pragma unroll
            for (int q = 0; q < 4; q++) {
                int j = tid + 256 * q;
                float arr2 = drow[j] + fp;
                float w    = fmaxf(0.0f, op[q] - arr2);
                float s    = arr2 + w;
                bool a1 = s <= cl[q];
                bool a2 = ((s + du[q]) + dl[q]) <= Tb;
                float v = (a1 && a2) ? nm[q] : 0.0f;
                if (j == i) v = 1.0f;
                orow[j] = v;
            }
        }
    }
}

extern "C" void kernel_launch(void* const* d_in, const int* in_sizes, int n_in,
                              void* d_out, int out_size)
{
    const float* inputs = (const float*)d_in[0];   // (B, N, 4) f32
    const float* dist   = (const float*)d_in[1];   // (N, N)   f32
    const float* mask   = (const float*)d_in[2];   // (B, N)   f32
    const float* ptime  = (const float*)d_in[3];   // (B, 1)   f32
    const int*   pres   = (const int*)d_in[4];     // (B,)     i32
    const int*   fut    = (const int*)d_in[5];     // (B,)     i32
    float* out = (float*)d_out;

    k_prep<<<BB, NN>>>(inputs, dist, mask, ptime, pres, fut, out);
    k_adj<<<(NN / RR) * (BB / BT), 256>>>(inputs, dist, out);
}